// round 13
// baseline (speedup 1.0000x reference)
#include <cuda_runtime.h>
#include <cuda_fp16.h>
#include <cstdint>
#include <cstddef>

#define BATCH 4096
#define OBS   512
#define ACT   32
#define H1D   1024
#define H2D   1024

// ---------------- static device scratch (no allocations) ----------------
static __device__ __align__(256) __half g_obs[(size_t)BATCH * OBS];           //   4 MB
static __device__ __align__(256) __half g_W1 [(size_t)ACT * OBS * H1D];       //  32 MB
static __device__ __align__(256) __half g_W2 [(size_t)ACT * H1D * H2D];       //  64 MB
static __device__ __align__(256) __half g_x1 [(size_t)ACT * BATCH * H1D];     // 256 MB
static __device__ int g_cnt[32];                    // per-m-block arrival counter

// ---------------- PTX helpers ----------------
__device__ __forceinline__ uint32_t s32(const void* p) {
    return (uint32_t)__cvta_generic_to_shared(p);
}
__device__ __forceinline__ void ldm_x4(uint32_t* r, uint32_t a) {
    asm volatile("ldmatrix.sync.aligned.m8n8.x4.shared.b16 {%0,%1,%2,%3}, [%4];"
                 : "=r"(r[0]), "=r"(r[1]), "=r"(r[2]), "=r"(r[3]) : "r"(a));
}
__device__ __forceinline__ void ldm_x4t(uint32_t* r, uint32_t a) {
    asm volatile("ldmatrix.sync.aligned.m8n8.x4.trans.shared.b16 {%0,%1,%2,%3}, [%4];"
                 : "=r"(r[0]), "=r"(r[1]), "=r"(r[2]), "=r"(r[3]) : "r"(a));
}
__device__ __forceinline__ void mma16816(float* d, const uint32_t* a, uint32_t b0, uint32_t b1) {
    asm volatile("mma.sync.aligned.m16n8k16.row.col.f32.f16.f16.f32 "
                 "{%0,%1,%2,%3}, {%4,%5,%6,%7}, {%8,%9}, {%0,%1,%2,%3};"
                 : "+f"(d[0]), "+f"(d[1]), "+f"(d[2]), "+f"(d[3])
                 : "r"(a[0]), "r"(a[1]), "r"(a[2]), "r"(a[3]), "r"(b0), "r"(b1));
}
__device__ __forceinline__ void cpa16(uint32_t dst, const void* src) {
    asm volatile("cp.async.cg.shared.global [%0], [%1], 16;" :: "r"(dst), "l"(src));
}
__device__ __forceinline__ void cpa_commit() { asm volatile("cp.async.commit_group;"); }
__device__ __forceinline__ float tanh_fast(float x) {
    float y;
    asm("tanh.approx.f32 %0, %1;" : "=f"(y) : "f"(x));
    return y;
}

// ---------------- fp32 -> fp16 conversion into static scratch ----------------
__global__ void f2h_kernel(const float* __restrict__ s, int sel, int n) {
    __half* d = (sel == 0) ? g_obs : ((sel == 1) ? g_W1 : g_W2);
    int i = (blockIdx.x * blockDim.x + threadIdx.x) * 8;
    if (i >= n) return;
    float4 v0 = *(const float4*)(s + i);
    float4 v1 = *(const float4*)(s + i + 4);
    *(__half2*)(d + i)     = __floats2half2_rn(v0.x, v0.y);
    *(__half2*)(d + i + 2) = __floats2half2_rn(v0.z, v0.w);
    *(__half2*)(d + i + 4) = __floats2half2_rn(v1.x, v1.y);
    *(__half2*)(d + i + 6) = __floats2half2_rn(v1.z, v1.w);
}

// ---------------- mu init: mu[b][a] = b3[a]; also zero arrival counters -------
__global__ void mu_init_kernel(const float* __restrict__ b3, float* __restrict__ mu) {
    int i = blockIdx.x * blockDim.x + threadIdx.x;     // 0 .. BATCH*ACT-1
    if (i < 32) g_cnt[i] = 0;
    if (i < BATCH * ACT) mu[i] = b3[i & 31];
}

// ---------------- batched GEMM + bias + tanh, BK=64, 3-stage pipeline ---------
// Tile: 128x128x64, 256 threads, 8 warps as 4(m) x 2(n), warp tile 32x64.
// IS_L1 == true : x1 = tanh.approx(obs @ W1[a] + b1[a]) stored fp16 (evict-first)
//                 via smem-transposed fully-coalesced epilogue.
// IS_L1 == false: fused layer-3 (mu atomics) + fused logp: the last CTA to
//                 finish each 128-row m-block computes logp for those rows.
#define SMEM_BYTES 108544
#define LOG2PI 1.8378770664093453f

template <int K, bool IS_L1>
__global__ void __launch_bounds__(256, 2) gemm_kernel(const float* __restrict__ bias,
                                                      const float* __restrict__ W3,
                                                      float* __restrict__ mu,
                                                      const float* __restrict__ act,
                                                      const float* __restrict__ lstd,
                                                      float* __restrict__ lp) {
    constexpr int BK = 64;
    extern __shared__ char smem[];
    auto sA    = (__half (*)[128][BK + 8])(smem);
    auto sB    = (__half (*)[BK][128 + 8])(smem + 55296);
    float* sBias = (float*)(smem + 107520);
    float* sW3   = (float*)(smem + 108032);

    const int a  = blockIdx.z;
    const int m0 = blockIdx.y * 128;
    const int n0 = blockIdx.x * 128;

    const __half* A  = IS_L1 ? (g_obs + (size_t)m0 * K)
                             : (g_x1 + ((size_t)a * BATCH + m0) * K);
    const __half* Bw = (IS_L1 ? g_W1 : g_W2) + (size_t)a * K * 1024 + n0;

    const int t = threadIdx.x;
    if (t < 128) {
        sBias[t] = bias[a * 1024 + n0 + t];
        if (!IS_L1) sW3[t] = W3[a * 1024 + n0 + t];
    }

    auto load = [&](int s, int kt) {
#pragma unroll
        for (int i = 0; i < 4; i++) {                       // A: 128 rows x 64 halves
            int c = t + i * 256;
            int r = c >> 3, c8 = (c & 7) * 8;
            cpa16(s32(&sA[s][r][c8]), A + (size_t)r * K + kt + c8);
        }
#pragma unroll
        for (int i = 0; i < 4; i++) {                       // B: 64 rows x 128 halves
            int c = t + i * 256;
            int r = c >> 4, c8 = (c & 15) * 8;
            cpa16(s32(&sB[s][r][c8]), Bw + (size_t)(kt + r) * 1024 + c8);
        }
    };

    const int lane = t & 31, warp = t >> 5;
    const int wm = warp >> 1, wn = warp & 1;

    float acc[2][8][4];
#pragma unroll
    for (int mi = 0; mi < 2; mi++)
#pragma unroll
        for (int ni = 0; ni < 8; ni++)
#pragma unroll
            for (int k = 0; k < 4; k++) acc[mi][ni][k] = 0.f;

    constexpr int NK = K / BK;

    // prologue: fill 2 of 3 stages
    load(0, 0);            cpa_commit();
    if (NK > 1) load(1, BK);
    cpa_commit();

    const int lrow  = lane & 15;
    const int lc8   = (lane >> 4) * 8;
    const int bkrow = lane & 7;
    const int bk8   = ((lane >> 3) & 1) * 8;
    const int bn8   = (lane >> 4) * 8;

    int s = 0;
    for (int kt = 0; kt < NK; kt++) {
        asm volatile("cp.async.wait_group 1;");
        __syncthreads();
        if (kt + 2 < NK) load((s + 2) % 3, (kt + 2) * BK);
        cpa_commit();

#pragma unroll
        for (int ks2 = 0; ks2 < 4; ks2++) {       // warp-staggered k16 order
            const int ks = (ks2 + warp) & 3;
            uint32_t af[2][4];
#pragma unroll
            for (int mi = 0; mi < 2; mi++)
                ldm_x4(af[mi], s32(&sA[s][wm * 32 + mi * 16 + lrow][ks * 16 + lc8]));
            uint32_t bf[4][4];
#pragma unroll
            for (int np = 0; np < 4; np++)
                ldm_x4t(bf[np], s32(&sB[s][ks * 16 + bk8 + bkrow][wn * 64 + np * 16 + bn8]));
#pragma unroll
            for (int mi = 0; mi < 2; mi++)
#pragma unroll
                for (int ni = 0; ni < 8; ni++) {
                    int np = ni >> 1, h = (ni & 1) * 2;
                    mma16816(acc[mi][ni], af[mi], bf[np][h], bf[np][h + 1]);
                }
        }
        s = (s + 1) % 3;
    }

    // ---------------- epilogue ----------------
    if (IS_L1) {
        // smem-transposed coalesced store: tile[128][136] halves reuses sA space.
        __syncthreads();                          // all warps done with smem stages
        auto tile = (__half (*)[136])(smem);
#pragma unroll
        for (int mi = 0; mi < 2; mi++) {
            int r0 = wm * 32 + mi * 16 + (lane >> 2);
#pragma unroll
            for (int ni = 0; ni < 8; ni++) {
                int cl = wn * 64 + ni * 8 + (lane & 3) * 2;
                float b0 = sBias[cl], b1 = sBias[cl + 1];
                float* d = acc[mi][ni];
                *(__half2*)&tile[r0][cl] =
                    __floats2half2_rn(tanh_fast(d[0] + b0), tanh_fast(d[1] + b1));
                *(__half2*)&tile[r0 + 8][cl] =
                    __floats2half2_rn(tanh_fast(d[2] + b0), tanh_fast(d[3] + b1));
            }
        }
        __syncthreads();
        {
            const int row = t >> 1, ch = (t & 1) * 64;
            const __half* src = &tile[row][ch];
            __half* dst = g_x1 + ((size_t)a * BATCH + m0 + row) * 1024 + n0 + ch;
#pragma unroll
            for (int i = 0; i < 8; i++)
                __stcs((uint4*)dst + i, *(const uint4*)(src + i * 8));
        }
    } else {
        float pmu[2][2] = {{0.f, 0.f}, {0.f, 0.f}};
#pragma unroll
        for (int mi = 0; mi < 2; mi++)
#pragma unroll
            for (int ni = 0; ni < 8; ni++) {
                int cl = wn * 64 + ni * 8 + (lane & 3) * 2;
                float b0 = sBias[cl], b1 = sBias[cl + 1];
                float w0 = sW3[cl],   w1 = sW3[cl + 1];
                float* d = acc[mi][ni];
                pmu[mi][0] += tanh_fast(d[0] + b0) * w0 + tanh_fast(d[1] + b1) * w1;
                pmu[mi][1] += tanh_fast(d[2] + b0) * w0 + tanh_fast(d[3] + b1) * w1;
            }
#pragma unroll
        for (int o = 1; o <= 2; o <<= 1)
#pragma unroll
            for (int mi = 0; mi < 2; mi++) {
                pmu[mi][0] += __shfl_xor_sync(0xffffffffu, pmu[mi][0], o);
                pmu[mi][1] += __shfl_xor_sync(0xffffffffu, pmu[mi][1], o);
            }
        if ((lane & 3) == 0) {
#pragma unroll
            for (int mi = 0; mi < 2; mi++) {
                int row = m0 + wm * 32 + mi * 16 + (lane >> 2);
                atomicAdd(mu + (size_t)row * 32 + a, pmu[mi][0]);
                atomicAdd(mu + (size_t)(row + 8) * 32 + a, pmu[mi][1]);
            }
        }

        // ---- fused logp: last CTA (of 256) per m-block computes lp rows ----
        __shared__ int sLast;
        __syncthreads();                 // all mu atomics of this CTA issued
        if (t == 0) {
            __threadfence();             // release: mu atomics before counter
            sLast = atomicAdd(&g_cnt[blockIdx.y], 1);
        }
        __syncthreads();
        if (sLast == 255) {
            __threadfence();             // acquire side
            if (t < 128) {
                const int b = m0 + t;
                const float4* mrow = (const float4*)(mu + (size_t)b * 32);
                const float4* arow = (const float4*)(act + (size_t)b * 32);
                float sum = 0.f;
#pragma unroll
                for (int q = 0; q < 8; q++) {
                    float4 m4 = __ldcg(mrow + q);
                    float4 a4 = __ldg(arow + q);
#pragma unroll
                    for (int j = 0; j < 4; j++) {
                        float l = __ldg(lstd + q * 4 + j);
                        float mv = (&m4.x)[j], av = (&a4.x)[j];
                        float z = (av - mv) * __expf(-l);
                        sum += -0.5f * (z * z + LOG2PI) - l;
                    }
                }
                lp[b] = sum;
            }
        }
    }
}

// ---------------- launch ------------------------------------------------------
extern "C" void kernel_launch(void* const* d_in, const int* in_sizes, int n_in,
                              void* d_out, int out_size) {
    const float* obs  = (const float*)d_in[0];
    const float* act  = (const float*)d_in[1];
    const float* W1   = (const float*)d_in[2];
    const float* b1   = (const float*)d_in[3];
    const float* W2   = (const float*)d_in[4];
    const float* b2   = (const float*)d_in[5];
    const float* W3   = (const float*)d_in[6];
    const float* b3   = (const float*)d_in[7];
    const float* lstd = (const float*)d_in[8];

    float* out = (float*)d_out;
    float* mu  = out;                              // [4096][32]
    float* lp  = out + (size_t)BATCH * ACT;        // [4096]

    static bool init_done = false;
    static cudaStream_t s2;
    static cudaEvent_t eFork, eObs, eJoin;
    if (!init_done) {
        cudaFuncSetAttribute(gemm_kernel<OBS, true>,
                             cudaFuncAttributeMaxDynamicSharedMemorySize, SMEM_BYTES);
        cudaFuncSetAttribute(gemm_kernel<H1D, false>,
                             cudaFuncAttributeMaxDynamicSharedMemorySize, SMEM_BYTES);
        cudaStreamCreateWithFlags(&s2, cudaStreamNonBlocking);
        cudaEventCreateWithFlags(&eFork, cudaEventDisableTiming);
        cudaEventCreateWithFlags(&eObs, cudaEventDisableTiming);
        cudaEventCreateWithFlags(&eJoin, cudaEventDisableTiming);
        init_done = true;
    }

    // Fork side stream: obs convert (needed by gemm1), then W2 + mu/cnt init
    // (needed only by gemm2) — hidden under f2h(W1) + gemm1.
    cudaEventRecord(eFork, 0);
    cudaStreamWaitEvent(s2, eFork, 0);
    f2h_kernel<<<(BATCH * OBS) / 2048, 256, 0, s2>>>(obs, 0, BATCH * OBS);
    cudaEventRecord(eObs, s2);
    f2h_kernel<<<(ACT * H1D * H2D) / 2048, 256, 0, s2>>>(W2, 2, ACT * H1D * H2D);
    mu_init_kernel<<<(BATCH * ACT) / 256, 256, 0, s2>>>(b3, mu);
    cudaEventRecord(eJoin, s2);

    // Main stream: W1 convert runs parallel to obs convert.
    f2h_kernel<<<(ACT * OBS * H1D) / 2048, 256>>>(W1, 1, ACT * OBS * H1D);
    cudaStreamWaitEvent(0, eObs, 0);

    gemm_kernel<OBS, true><<<dim3(8, 32, 32), 256, SMEM_BYTES>>>(
        b1, nullptr, nullptr, nullptr, nullptr, nullptr);

    cudaStreamWaitEvent(0, eJoin, 0);

    gemm_kernel<H1D, false><<<dim3(8, 32, 32), 256, SMEM_BYTES>>>(
        b2, W3, mu, act, lstd, lp);
}

// round 14
// speedup vs baseline: 1.0263x; 1.0263x over previous
#include <cuda_runtime.h>
#include <cuda_fp16.h>
#include <cstdint>
#include <cstddef>

#define BATCH 4096
#define OBS   512
#define ACT   32
#define H1D   1024
#define H2D   1024

// ---------------- static device scratch (no allocations) ----------------
static __device__ __align__(256) __half g_obs[(size_t)BATCH * OBS];           //   4 MB
static __device__ __align__(256) __half g_W1 [(size_t)ACT * OBS * H1D];       //  32 MB
static __device__ __align__(256) __half g_W2 [(size_t)ACT * H1D * H2D];       //  64 MB
static __device__ __align__(256) __half g_x1 [(size_t)ACT * BATCH * H1D];     // 256 MB
static __device__ int g_cnt[32];                    // per-m-block arrival counter

// ---------------- PTX helpers ----------------
__device__ __forceinline__ uint32_t s32(const void* p) {
    return (uint32_t)__cvta_generic_to_shared(p);
}
__device__ __forceinline__ void ldm_x4(uint32_t* r, uint32_t a) {
    asm volatile("ldmatrix.sync.aligned.m8n8.x4.shared.b16 {%0,%1,%2,%3}, [%4];"
                 : "=r"(r[0]), "=r"(r[1]), "=r"(r[2]), "=r"(r[3]) : "r"(a));
}
__device__ __forceinline__ void ldm_x4t(uint32_t* r, uint32_t a) {
    asm volatile("ldmatrix.sync.aligned.m8n8.x4.trans.shared.b16 {%0,%1,%2,%3}, [%4];"
                 : "=r"(r[0]), "=r"(r[1]), "=r"(r[2]), "=r"(r[3]) : "r"(a));
}
__device__ __forceinline__ void mma16816(float* d, const uint32_t* a, uint32_t b0, uint32_t b1) {
    asm volatile("mma.sync.aligned.m16n8k16.row.col.f32.f16.f16.f32 "
                 "{%0,%1,%2,%3}, {%4,%5,%6,%7}, {%8,%9}, {%0,%1,%2,%3};"
                 : "+f"(d[0]), "+f"(d[1]), "+f"(d[2]), "+f"(d[3])
                 : "r"(a[0]), "r"(a[1]), "r"(a[2]), "r"(a[3]), "r"(b0), "r"(b1));
}
__device__ __forceinline__ void cpa16(uint32_t dst, const void* src) {
    asm volatile("cp.async.cg.shared.global [%0], [%1], 16;" :: "r"(dst), "l"(src));
}
__device__ __forceinline__ void cpa_commit() { asm volatile("cp.async.commit_group;"); }
__device__ __forceinline__ float tanh_fast(float x) {
    float y;
    asm("tanh.approx.f32 %0, %1;" : "=f"(y) : "f"(x));
    return y;
}

// ---------------- fp32 -> fp16 conversion into static scratch ----------------
__global__ void f2h_kernel(const float* __restrict__ s, int sel, int n) {
    __half* d = (sel == 0) ? g_obs : ((sel == 1) ? g_W1 : g_W2);
    int i = (blockIdx.x * blockDim.x + threadIdx.x) * 8;
    if (i >= n) return;
    float4 v0 = *(const float4*)(s + i);
    float4 v1 = *(const float4*)(s + i + 4);
    *(__half2*)(d + i)     = __floats2half2_rn(v0.x, v0.y);
    *(__half2*)(d + i + 2) = __floats2half2_rn(v0.z, v0.w);
    *(__half2*)(d + i + 4) = __floats2half2_rn(v1.x, v1.y);
    *(__half2*)(d + i + 6) = __floats2half2_rn(v1.z, v1.w);
}

// ---------------- mu init: mu[b][a] = b3[a]; also zero arrival counters -------
__global__ void mu_init_kernel(const float* __restrict__ b3, float* __restrict__ mu) {
    int i = blockIdx.x * blockDim.x + threadIdx.x;     // 0 .. BATCH*ACT-1
    if (i < 32) g_cnt[i] = 0;
    if (i < BATCH * ACT) mu[i] = b3[i & 31];
}

// ---------------- batched GEMM + bias + tanh, BK=64, 3-stage pipeline ---------
// Tile: 128x128x64, 256 threads, 8 warps as 4(m) x 2(n), warp tile 32x64.
// IS_L1 == true : x1 = tanh.approx(obs @ W1[a] + b1[a]) stored fp16 (plain
//                 stores — keep x1 L2-resident for gemm2) via smem-transposed
//                 fully-coalesced epilogue.
// IS_L1 == false: fused layer-3 (mu atomics) + fused logp: the last CTA to
//                 finish each 128-row m-block computes logp for those rows.
#define SMEM_BYTES 108544
#define LOG2PI 1.8378770664093453f

template <int K, bool IS_L1>
__global__ void __launch_bounds__(256, 2) gemm_kernel(const float* __restrict__ bias,
                                                      const float* __restrict__ W3,
                                                      float* __restrict__ mu,
                                                      const float* __restrict__ act,
                                                      const float* __restrict__ lstd,
                                                      float* __restrict__ lp) {
    constexpr int BK = 64;
    extern __shared__ char smem[];
    auto sA    = (__half (*)[128][BK + 8])(smem);
    auto sB    = (__half (*)[BK][128 + 8])(smem + 55296);
    float* sBias = (float*)(smem + 107520);
    float* sW3   = (float*)(smem + 108032);

    const int a  = blockIdx.z;
    const int m0 = blockIdx.y * 128;
    const int n0 = blockIdx.x * 128;

    const __half* A  = IS_L1 ? (g_obs + (size_t)m0 * K)
                             : (g_x1 + ((size_t)a * BATCH + m0) * K);
    const __half* Bw = (IS_L1 ? g_W1 : g_W2) + (size_t)a * K * 1024 + n0;

    const int t = threadIdx.x;
    if (t < 128) {
        sBias[t] = bias[a * 1024 + n0 + t];
        if (!IS_L1) sW3[t] = W3[a * 1024 + n0 + t];
    }

    auto load = [&](int s, int kt) {
#pragma unroll
        for (int i = 0; i < 4; i++) {                       // A: 128 rows x 64 halves
            int c = t + i * 256;
            int r = c >> 3, c8 = (c & 7) * 8;
            cpa16(s32(&sA[s][r][c8]), A + (size_t)r * K + kt + c8);
        }
#pragma unroll
        for (int i = 0; i < 4; i++) {                       // B: 64 rows x 128 halves
            int c = t + i * 256;
            int r = c >> 4, c8 = (c & 15) * 8;
            cpa16(s32(&sB[s][r][c8]), Bw + (size_t)(kt + r) * 1024 + c8);
        }
    };

    const int lane = t & 31, warp = t >> 5;
    const int wm = warp >> 1, wn = warp & 1;

    float acc[2][8][4];
#pragma unroll
    for (int mi = 0; mi < 2; mi++)
#pragma unroll
        for (int ni = 0; ni < 8; ni++)
#pragma unroll
            for (int k = 0; k < 4; k++) acc[mi][ni][k] = 0.f;

    constexpr int NK = K / BK;

    // prologue: fill 2 of 3 stages
    load(0, 0);            cpa_commit();
    if (NK > 1) load(1, BK);
    cpa_commit();

    const int lrow  = lane & 15;
    const int lc8   = (lane >> 4) * 8;
    const int bkrow = lane & 7;
    const int bk8   = ((lane >> 3) & 1) * 8;
    const int bn8   = (lane >> 4) * 8;

    int s = 0;
    for (int kt = 0; kt < NK; kt++) {
        asm volatile("cp.async.wait_group 1;");
        __syncthreads();
        if (kt + 2 < NK) load((s + 2) % 3, (kt + 2) * BK);
        cpa_commit();

#pragma unroll
        for (int ks2 = 0; ks2 < 4; ks2++) {       // warp-staggered k16 order
            const int ks = (ks2 + warp) & 3;
            uint32_t af[2][4];
#pragma unroll
            for (int mi = 0; mi < 2; mi++)
                ldm_x4(af[mi], s32(&sA[s][wm * 32 + mi * 16 + lrow][ks * 16 + lc8]));
            uint32_t bf[4][4];
#pragma unroll
            for (int np = 0; np < 4; np++)
                ldm_x4t(bf[np], s32(&sB[s][ks * 16 + bk8 + bkrow][wn * 64 + np * 16 + bn8]));
#pragma unroll
            for (int mi = 0; mi < 2; mi++)
#pragma unroll
                for (int ni = 0; ni < 8; ni++) {
                    int np = ni >> 1, h = (ni & 1) * 2;
                    mma16816(acc[mi][ni], af[mi], bf[np][h], bf[np][h + 1]);
                }
        }
        s = (s + 1) % 3;
    }

    // ---------------- epilogue ----------------
    if (IS_L1) {
        // smem-transposed coalesced store: tile[128][136] halves reuses sA space.
        __syncthreads();                          // all warps done with smem stages
        auto tile = (__half (*)[136])(smem);
#pragma unroll
        for (int mi = 0; mi < 2; mi++) {
            int r0 = wm * 32 + mi * 16 + (lane >> 2);
#pragma unroll
            for (int ni = 0; ni < 8; ni++) {
                int cl = wn * 64 + ni * 8 + (lane & 3) * 2;
                float b0 = sBias[cl], b1 = sBias[cl + 1];
                float* d = acc[mi][ni];
                *(__half2*)&tile[r0][cl] =
                    __floats2half2_rn(tanh_fast(d[0] + b0), tanh_fast(d[1] + b1));
                *(__half2*)&tile[r0 + 8][cl] =
                    __floats2half2_rn(tanh_fast(d[2] + b0), tanh_fast(d[3] + b1));
            }
        }
        __syncthreads();
        {
            const int row = t >> 1, ch = (t & 1) * 64;
            const __half* src = &tile[row][ch];
            __half* dst = g_x1 + ((size_t)a * BATCH + m0 + row) * 1024 + n0 + ch;
#pragma unroll
            for (int i = 0; i < 8; i++)
                ((uint4*)dst)[i] = *(const uint4*)(src + i * 8);
        }
    } else {
        float pmu[2][2] = {{0.f, 0.f}, {0.f, 0.f}};
#pragma unroll
        for (int mi = 0; mi < 2; mi++)
#pragma unroll
            for (int ni = 0; ni < 8; ni++) {
                int cl = wn * 64 + ni * 8 + (lane & 3) * 2;
                float b0 = sBias[cl], b1 = sBias[cl + 1];
                float w0 = sW3[cl],   w1 = sW3[cl + 1];
                float* d = acc[mi][ni];
                pmu[mi][0] += tanh_fast(d[0] + b0) * w0 + tanh_fast(d[1] + b1) * w1;
                pmu[mi][1] += tanh_fast(d[2] + b0) * w0 + tanh_fast(d[3] + b1) * w1;
            }
#pragma unroll
        for (int o = 1; o <= 2; o <<= 1)
#pragma unroll
            for (int mi = 0; mi < 2; mi++) {
                pmu[mi][0] += __shfl_xor_sync(0xffffffffu, pmu[mi][0], o);
                pmu[mi][1] += __shfl_xor_sync(0xffffffffu, pmu[mi][1], o);
            }
        if ((lane & 3) == 0) {
#pragma unroll
            for (int mi = 0; mi < 2; mi++) {
                int row = m0 + wm * 32 + mi * 16 + (lane >> 2);
                atomicAdd(mu + (size_t)row * 32 + a, pmu[mi][0]);
                atomicAdd(mu + (size_t)(row + 8) * 32 + a, pmu[mi][1]);
            }
        }

        // ---- fused logp: last CTA (of 256) per m-block computes lp rows ----
        __shared__ int sLast;
        __syncthreads();                 // all mu atomics of this CTA issued
        if (t == 0) {
            __threadfence();             // release: mu atomics before counter
            sLast = atomicAdd(&g_cnt[blockIdx.y], 1);
        }
        __syncthreads();
        if (sLast == 255) {
            __threadfence();             // acquire side
            if (t < 128) {
                const int b = m0 + t;
                const float4* mrow = (const float4*)(mu + (size_t)b * 32);
                const float4* arow = (const float4*)(act + (size_t)b * 32);
                float sum = 0.f;
#pragma unroll
                for (int q = 0; q < 8; q++) {
                    float4 m4 = __ldcg(mrow + q);
                    float4 a4 = __ldg(arow + q);
#pragma unroll
                    for (int j = 0; j < 4; j++) {
                        float l = __ldg(lstd + q * 4 + j);
                        float mv = (&m4.x)[j], av = (&a4.x)[j];
                        float z = (av - mv) * __expf(-l);
                        sum += -0.5f * (z * z + LOG2PI) - l;
                    }
                }
                lp[b] = sum;
            }
        }
    }
}

// ---------------- launch ------------------------------------------------------
extern "C" void kernel_launch(void* const* d_in, const int* in_sizes, int n_in,
                              void* d_out, int out_size) {
    const float* obs  = (const float*)d_in[0];
    const float* act  = (const float*)d_in[1];
    const float* W1   = (const float*)d_in[2];
    const float* b1   = (const float*)d_in[3];
    const float* W2   = (const float*)d_in[4];
    const float* b2   = (const float*)d_in[5];
    const float* W3   = (const float*)d_in[6];
    const float* b3   = (const float*)d_in[7];
    const float* lstd = (const float*)d_in[8];

    float* out = (float*)d_out;
    float* mu  = out;                              // [4096][32]
    float* lp  = out + (size_t)BATCH * ACT;        // [4096]

    static bool init_done = false;
    static cudaStream_t s2;
    static cudaEvent_t eFork, eObs, eJoin;
    if (!init_done) {
        cudaFuncSetAttribute(gemm_kernel<OBS, true>,
                             cudaFuncAttributeMaxDynamicSharedMemorySize, SMEM_BYTES);
        cudaFuncSetAttribute(gemm_kernel<H1D, false>,
                             cudaFuncAttributeMaxDynamicSharedMemorySize, SMEM_BYTES);
        cudaStreamCreateWithFlags(&s2, cudaStreamNonBlocking);
        cudaEventCreateWithFlags(&eFork, cudaEventDisableTiming);
        cudaEventCreateWithFlags(&eObs, cudaEventDisableTiming);
        cudaEventCreateWithFlags(&eJoin, cudaEventDisableTiming);
        init_done = true;
    }

    // Fork side stream: obs convert (needed by gemm1), then W2 + mu/cnt init
    // (needed only by gemm2) — hidden under f2h(W1) + gemm1.
    cudaEventRecord(eFork, 0);
    cudaStreamWaitEvent(s2, eFork, 0);
    f2h_kernel<<<(BATCH * OBS) / 2048, 256, 0, s2>>>(obs, 0, BATCH * OBS);
    cudaEventRecord(eObs, s2);
    f2h_kernel<<<(ACT * H1D * H2D) / 2048, 256, 0, s2>>>(W2, 2, ACT * H1D * H2D);
    mu_init_kernel<<<(BATCH * ACT) / 256, 256, 0, s2>>>(b3, mu);
    cudaEventRecord(eJoin, s2);

    // Main stream: W1 convert runs parallel to obs convert.
    f2h_kernel<<<(ACT * OBS * H1D) / 2048, 256>>>(W1, 1, ACT * OBS * H1D);
    cudaStreamWaitEvent(0, eObs, 0);

    gemm_kernel<OBS, true><<<dim3(8, 32, 32), 256, SMEM_BYTES>>>(
        b1, nullptr, nullptr, nullptr, nullptr, nullptr);

    cudaStreamWaitEvent(0, eJoin, 0);

    gemm_kernel<H1D, false><<<dim3(8, 32, 32), 256, SMEM_BYTES>>>(
        b2, W3, mu, act, lstd, lp);
}

// round 15
// speedup vs baseline: 1.0531x; 1.0262x over previous
#include <cuda_runtime.h>
#include <cuda_fp16.h>
#include <cstdint>
#include <cstddef>

#define BATCH 4096
#define OBS   512
#define ACT   32
#define H1D   1024
#define H2D   1024

// ---------------- static device scratch (no allocations) ----------------
static __device__ __align__(256) __half g_obs[(size_t)BATCH * OBS];           //   4 MB
static __device__ __align__(256) __half g_W1 [(size_t)ACT * OBS * H1D];       //  32 MB
static __device__ __align__(256) __half g_W2 [(size_t)ACT * H1D * H2D];       //  64 MB
static __device__ __align__(256) __half g_x1 [(size_t)ACT * BATCH * H1D];     // 256 MB

// ---------------- PTX helpers ----------------
__device__ __forceinline__ uint32_t s32(const void* p) {
    return (uint32_t)__cvta_generic_to_shared(p);
}
__device__ __forceinline__ void ldm_x4(uint32_t* r, uint32_t a) {
    asm volatile("ldmatrix.sync.aligned.m8n8.x4.shared.b16 {%0,%1,%2,%3}, [%4];"
                 : "=r"(r[0]), "=r"(r[1]), "=r"(r[2]), "=r"(r[3]) : "r"(a));
}
__device__ __forceinline__ void ldm_x4t(uint32_t* r, uint32_t a) {
    asm volatile("ldmatrix.sync.aligned.m8n8.x4.trans.shared.b16 {%0,%1,%2,%3}, [%4];"
                 : "=r"(r[0]), "=r"(r[1]), "=r"(r[2]), "=r"(r[3]) : "r"(a));
}
__device__ __forceinline__ void mma16816(float* d, const uint32_t* a, uint32_t b0, uint32_t b1) {
    asm volatile("mma.sync.aligned.m16n8k16.row.col.f32.f16.f16.f32 "
                 "{%0,%1,%2,%3}, {%4,%5,%6,%7}, {%8,%9}, {%0,%1,%2,%3};"
                 : "+f"(d[0]), "+f"(d[1]), "+f"(d[2]), "+f"(d[3])
                 : "r"(a[0]), "r"(a[1]), "r"(a[2]), "r"(a[3]), "r"(b0), "r"(b1));
}
__device__ __forceinline__ void cpa16(uint32_t dst, const void* src) {
    asm volatile("cp.async.cg.shared.global [%0], [%1], 16;" :: "r"(dst), "l"(src));
}
__device__ __forceinline__ void cpa_commit() { asm volatile("cp.async.commit_group;"); }
__device__ __forceinline__ float tanh_fast(float x) {
    float y;
    asm("tanh.approx.f32 %0, %1;" : "=f"(y) : "f"(x));
    return y;
}

// ---------------- fp32 -> fp16 conversion into static scratch ----------------
__global__ void f2h_kernel(const float* __restrict__ s, int sel, int n) {
    __half* d = (sel == 0) ? g_obs : ((sel == 1) ? g_W1 : g_W2);
    int i = (blockIdx.x * blockDim.x + threadIdx.x) * 8;
    if (i >= n) return;
    float4 v0 = *(const float4*)(s + i);
    float4 v1 = *(const float4*)(s + i + 4);
    *(__half2*)(d + i)     = __floats2half2_rn(v0.x, v0.y);
    *(__half2*)(d + i + 2) = __floats2half2_rn(v0.z, v0.w);
    *(__half2*)(d + i + 4) = __floats2half2_rn(v1.x, v1.y);
    *(__half2*)(d + i + 6) = __floats2half2_rn(v1.z, v1.w);
}

// ---------------- mu init: mu[b][a] = b3[a] ----------------
__global__ void mu_init_kernel(const float* __restrict__ b3, float* __restrict__ mu) {
    int i = blockIdx.x * blockDim.x + threadIdx.x;     // 0 .. BATCH*ACT-1
    if (i < BATCH * ACT) mu[i] = b3[i & 31];
}

// ---------------- batched GEMM + bias + tanh, BK=64, 3-stage pipeline ---------
// Tile: 128x128x64, 256 threads, 8 warps as 4(m) x 2(n), warp tile 32x64.
// IS_L1 == true : x1 = tanh.approx(obs @ W1[a] + b1[a]) stored fp16, with a
//                 smem-transposed fully-coalesced store epilogue.
// IS_L1 == false: fused layer-3; mu[m][a] += sum_n tanh.approx(.) * W3[a][n]
#define SMEM_BYTES 108544

template <int K, bool IS_L1>
__global__ void __launch_bounds__(256, 2) gemm_kernel(const float* __restrict__ bias,
                                                      const float* __restrict__ W3,
                                                      float* __restrict__ mu) {
    constexpr int BK = 64;
    extern __shared__ char smem[];
    auto sA    = (__half (*)[128][BK + 8])(smem);
    auto sB    = (__half (*)[BK][128 + 8])(smem + 55296);
    float* sBias = (float*)(smem + 107520);
    float* sW3   = (float*)(smem + 108032);

    const int a  = blockIdx.z;
    const int m0 = blockIdx.y * 128;
    const int n0 = blockIdx.x * 128;

    const __half* A  = IS_L1 ? (g_obs + (size_t)m0 * K)
                             : (g_x1 + ((size_t)a * BATCH + m0) * K);
    const __half* Bw = (IS_L1 ? g_W1 : g_W2) + (size_t)a * K * 1024 + n0;

    const int t = threadIdx.x;
    if (t < 128) {
        sBias[t] = bias[a * 1024 + n0 + t];
        if (!IS_L1) sW3[t] = W3[a * 1024 + n0 + t];
    }

    auto load = [&](int s, int kt) {
#pragma unroll
        for (int i = 0; i < 4; i++) {                       // A: 128 rows x 64 halves
            int c = t + i * 256;
            int r = c >> 3, c8 = (c & 7) * 8;
            cpa16(s32(&sA[s][r][c8]), A + (size_t)r * K + kt + c8);
        }
#pragma unroll
        for (int i = 0; i < 4; i++) {                       // B: 64 rows x 128 halves
            int c = t + i * 256;
            int r = c >> 4, c8 = (c & 15) * 8;
            cpa16(s32(&sB[s][r][c8]), Bw + (size_t)(kt + r) * 1024 + c8);
        }
    };

    const int lane = t & 31, warp = t >> 5;
    const int wm = warp >> 1, wn = warp & 1;

    float acc[2][8][4];
#pragma unroll
    for (int mi = 0; mi < 2; mi++)
#pragma unroll
        for (int ni = 0; ni < 8; ni++)
#pragma unroll
            for (int k = 0; k < 4; k++) acc[mi][ni][k] = 0.f;

    constexpr int NK = K / BK;

    // prologue: fill 2 of 3 stages
    load(0, 0);            cpa_commit();
    if (NK > 1) load(1, BK);
    cpa_commit();

    const int lrow  = lane & 15;
    const int lc8   = (lane >> 4) * 8;
    const int bkrow = lane & 7;
    const int bk8   = ((lane >> 3) & 1) * 8;
    const int bn8   = (lane >> 4) * 8;

    int s = 0;
    for (int kt = 0; kt < NK; kt++) {
        asm volatile("cp.async.wait_group 1;");
        __syncthreads();
        if (kt + 2 < NK) load((s + 2) % 3, (kt + 2) * BK);
        cpa_commit();

#pragma unroll
        for (int ks2 = 0; ks2 < 4; ks2++) {       // warp-staggered k16 order
            const int ks = (ks2 + warp) & 3;
            uint32_t af[2][4];
#pragma unroll
            for (int mi = 0; mi < 2; mi++)
                ldm_x4(af[mi], s32(&sA[s][wm * 32 + mi * 16 + lrow][ks * 16 + lc8]));
            uint32_t bf[4][4];
#pragma unroll
            for (int np = 0; np < 4; np++)
                ldm_x4t(bf[np], s32(&sB[s][ks * 16 + bk8 + bkrow][wn * 64 + np * 16 + bn8]));
#pragma unroll
            for (int mi = 0; mi < 2; mi++)
#pragma unroll
                for (int ni = 0; ni < 8; ni++) {
                    int np = ni >> 1, h = (ni & 1) * 2;
                    mma16816(acc[mi][ni], af[mi], bf[np][h], bf[np][h + 1]);
                }
        }
        s = (s + 1) % 3;
    }

    // ---------------- epilogue ----------------
    if (IS_L1) {
        // smem-transposed coalesced store: tile[128][136] halves reuses sA space.
        __syncthreads();                          // all warps done with smem stages
        auto tile = (__half (*)[136])(smem);
#pragma unroll
        for (int mi = 0; mi < 2; mi++) {
            int r0 = wm * 32 + mi * 16 + (lane >> 2);
#pragma unroll
            for (int ni = 0; ni < 8; ni++) {
                int cl = wn * 64 + ni * 8 + (lane & 3) * 2;
                float b0 = sBias[cl], b1 = sBias[cl + 1];
                float* d = acc[mi][ni];
                *(__half2*)&tile[r0][cl] =
                    __floats2half2_rn(tanh_fast(d[0] + b0), tanh_fast(d[1] + b1));
                *(__half2*)&tile[r0 + 8][cl] =
                    __floats2half2_rn(tanh_fast(d[2] + b0), tanh_fast(d[3] + b1));
            }
        }
        __syncthreads();
        // 256 threads: thread t stores row t>>1, 64-col half (t&1)*64 as 8x16B
        {
            const int row = t >> 1, ch = (t & 1) * 64;
            const __half* src = &tile[row][ch];
            __half* dst = g_x1 + ((size_t)a * BATCH + m0 + row) * 1024 + n0 + ch;
#pragma unroll
            for (int i = 0; i < 8; i++)
                ((uint4*)dst)[i] = *(const uint4*)(src + i * 8);
        }
    } else {
        float pmu[2][2] = {{0.f, 0.f}, {0.f, 0.f}};
#pragma unroll
        for (int mi = 0; mi < 2; mi++)
#pragma unroll
            for (int ni = 0; ni < 8; ni++) {
                int cl = wn * 64 + ni * 8 + (lane & 3) * 2;
                float b0 = sBias[cl], b1 = sBias[cl + 1];
                float w0 = sW3[cl],   w1 = sW3[cl + 1];
                float* d = acc[mi][ni];
                pmu[mi][0] += tanh_fast(d[0] + b0) * w0 + tanh_fast(d[1] + b1) * w1;
                pmu[mi][1] += tanh_fast(d[2] + b0) * w0 + tanh_fast(d[3] + b1) * w1;
            }
#pragma unroll
        for (int o = 1; o <= 2; o <<= 1)
#pragma unroll
            for (int mi = 0; mi < 2; mi++) {
                pmu[mi][0] += __shfl_xor_sync(0xffffffffu, pmu[mi][0], o);
                pmu[mi][1] += __shfl_xor_sync(0xffffffffu, pmu[mi][1], o);
            }
        if ((lane & 3) == 0) {
#pragma unroll
            for (int mi = 0; mi < 2; mi++) {
                int row = m0 + wm * 32 + mi * 16 + (lane >> 2);
                atomicAdd(mu + (size_t)row * 32 + a, pmu[mi][0]);
                atomicAdd(mu + (size_t)(row + 8) * 32 + a, pmu[mi][1]);
            }
        }
    }
}

// ---------------- logp --------------------------------------------------------
__global__ void logp_kernel(const float* __restrict__ mu, const float* __restrict__ act,
                            const float* __restrict__ ls, float* __restrict__ lp) {
    int b = blockIdx.x * blockDim.x + threadIdx.x;
    if (b >= BATCH) return;
    float s = 0.f;
#pragma unroll
    for (int a = 0; a < 32; a++) {
        float l = ls[a];
        float z = (act[b * 32 + a] - mu[b * 32 + a]) * __expf(-l);
        s += -0.5f * (z * z + 1.8378770664093453f) - l;
    }
    lp[b] = s;
}

// ---------------- launch ------------------------------------------------------
extern "C" void kernel_launch(void* const* d_in, const int* in_sizes, int n_in,
                              void* d_out, int out_size) {
    const float* obs  = (const float*)d_in[0];
    const float* act  = (const float*)d_in[1];
    const float* W1   = (const float*)d_in[2];
    const float* b1   = (const float*)d_in[3];
    const float* W2   = (const float*)d_in[4];
    const float* b2   = (const float*)d_in[5];
    const float* W3   = (const float*)d_in[6];
    const float* b3   = (const float*)d_in[7];
    const float* lstd = (const float*)d_in[8];

    float* out = (float*)d_out;
    float* mu  = out;                              // [4096][32]
    float* lp  = out + (size_t)BATCH * ACT;        // [4096]

    static bool init_done = false;
    static cudaStream_t s2;
    static cudaEvent_t eFork, eObs, eJoin;
    if (!init_done) {
        cudaFuncSetAttribute(gemm_kernel<OBS, true>,
                             cudaFuncAttributeMaxDynamicSharedMemorySize, SMEM_BYTES);
        cudaFuncSetAttribute(gemm_kernel<H1D, false>,
                             cudaFuncAttributeMaxDynamicSharedMemorySize, SMEM_BYTES);
        cudaStreamCreateWithFlags(&s2, cudaStreamNonBlocking);
        cudaEventCreateWithFlags(&eFork, cudaEventDisableTiming);
        cudaEventCreateWithFlags(&eObs, cudaEventDisableTiming);
        cudaEventCreateWithFlags(&eJoin, cudaEventDisableTiming);
        init_done = true;
    }

    // Fork side stream: obs convert (fast, needed by gemm1), then W2 + mu init
    // (needed only by gemm2) — all hidden under f2h(W1) + gemm1.
    cudaEventRecord(eFork, 0);
    cudaStreamWaitEvent(s2, eFork, 0);
    f2h_kernel<<<(BATCH * OBS) / 2048, 256, 0, s2>>>(obs, 0, BATCH * OBS);
    cudaEventRecord(eObs, s2);
    f2h_kernel<<<(ACT * H1D * H2D) / 2048, 256, 0, s2>>>(W2, 2, ACT * H1D * H2D);
    mu_init_kernel<<<(BATCH * ACT) / 256, 256, 0, s2>>>(b3, mu);
    cudaEventRecord(eJoin, s2);

    // Main stream: W1 convert runs parallel to obs convert.
    f2h_kernel<<<(ACT * OBS * H1D) / 2048, 256>>>(W1, 1, ACT * OBS * H1D);
    cudaStreamWaitEvent(0, eObs, 0);

    gemm_kernel<OBS, true><<<dim3(8, 32, 32), 256, SMEM_BYTES>>>(b1, nullptr, nullptr);

    // Join: gemm2 needs W2 (s2) and x1 (main stream).
    cudaStreamWaitEvent(0, eJoin, 0);

    gemm_kernel<H1D, false><<<dim3(8, 32, 32), 256, SMEM_BYTES>>>(b2, W3, mu);

    logp_kernel<<<(BATCH + 255) / 256, 256>>>(mu, act, lstd, lp);
}

// round 16
// speedup vs baseline: 1.0532x; 1.0001x over previous
#include <cuda_runtime.h>
#include <cuda_fp16.h>
#include <cstdint>
#include <cstddef>

#define BATCH 4096
#define OBS   512
#define ACT   32
#define H1D   1024
#define H2D   1024

// ---------------- static device scratch (no allocations) ----------------
static __device__ __align__(256) __half g_obs[(size_t)BATCH * OBS];           //   4 MB
static __device__ __align__(256) __half g_W1 [(size_t)ACT * OBS * H1D];       //  32 MB
static __device__ __align__(256) __half g_W2 [(size_t)ACT * H1D * H2D];       //  64 MB
static __device__ __align__(256) __half g_x1 [(size_t)ACT * BATCH * H1D];     // 256 MB

// ---------------- PTX helpers ----------------
__device__ __forceinline__ uint32_t s32(const void* p) {
    return (uint32_t)__cvta_generic_to_shared(p);
}
__device__ __forceinline__ void ldm_x4(uint32_t* r, uint32_t a) {
    asm volatile("ldmatrix.sync.aligned.m8n8.x4.shared.b16 {%0,%1,%2,%3}, [%4];"
                 : "=r"(r[0]), "=r"(r[1]), "=r"(r[2]), "=r"(r[3]) : "r"(a));
}
__device__ __forceinline__ void ldm_x4t(uint32_t* r, uint32_t a) {
    asm volatile("ldmatrix.sync.aligned.m8n8.x4.trans.shared.b16 {%0,%1,%2,%3}, [%4];"
                 : "=r"(r[0]), "=r"(r[1]), "=r"(r[2]), "=r"(r[3]) : "r"(a));
}
__device__ __forceinline__ void mma16816(float* d, const uint32_t* a, uint32_t b0, uint32_t b1) {
    asm volatile("mma.sync.aligned.m16n8k16.row.col.f32.f16.f16.f32 "
                 "{%0,%1,%2,%3}, {%4,%5,%6,%7}, {%8,%9}, {%0,%1,%2,%3};"
                 : "+f"(d[0]), "+f"(d[1]), "+f"(d[2]), "+f"(d[3])
                 : "r"(a[0]), "r"(a[1]), "r"(a[2]), "r"(a[3]), "r"(b0), "r"(b1));
}
__device__ __forceinline__ void cpa16(uint32_t dst, const void* src) {
    asm volatile("cp.async.cg.shared.global [%0], [%1], 16;" :: "r"(dst), "l"(src));
}
__device__ __forceinline__ void cpa_commit() { asm volatile("cp.async.commit_group;"); }
__device__ __forceinline__ float tanh_fast(float x) {
    float y;
    asm("tanh.approx.f32 %0, %1;" : "=f"(y) : "f"(x));
    return y;
}

// ---------------- fp32 -> fp16 conversion into static scratch ----------------
// Converts n elements starting at element offset `off` within target `sel`.
__global__ void f2h_kernel(const float* __restrict__ s, int sel, int off, int n) {
    __half* d = (sel == 0) ? g_obs : ((sel == 1) ? g_W1 : g_W2);
    int i = off + (blockIdx.x * blockDim.x + threadIdx.x) * 8;
    if (i >= off + n) return;
    float4 v0 = *(const float4*)(s + i);
    float4 v1 = *(const float4*)(s + i + 4);
    *(__half2*)(d + i)     = __floats2half2_rn(v0.x, v0.y);
    *(__half2*)(d + i + 2) = __floats2half2_rn(v0.z, v0.w);
    *(__half2*)(d + i + 4) = __floats2half2_rn(v1.x, v1.y);
    *(__half2*)(d + i + 6) = __floats2half2_rn(v1.z, v1.w);
}

// ---------------- mu init: mu[b][a] = b3[a] ----------------
__global__ void mu_init_kernel(const float* __restrict__ b3, float* __restrict__ mu) {
    int i = blockIdx.x * blockDim.x + threadIdx.x;     // 0 .. BATCH*ACT-1
    if (i < BATCH * ACT) mu[i] = b3[i & 31];
}

// ---------------- batched GEMM + bias + tanh, BK=64, 3-stage pipeline ---------
// Tile: 128x128x64, 256 threads, 8 warps as 4(m) x 2(n), warp tile 32x64.
// IS_L1 == true : x1 = tanh.approx(obs @ W1[a] + b1[a]) stored fp16, with a
//                 smem-transposed fully-coalesced store epilogue.
// IS_L1 == false: fused layer-3; mu[m][a] += sum_n tanh.approx(.) * W3[a][n]
#define SMEM_BYTES 108544

template <int K, bool IS_L1>
__global__ void __launch_bounds__(256, 2) gemm_kernel(const float* __restrict__ bias,
                                                      const float* __restrict__ W3,
                                                      float* __restrict__ mu) {
    constexpr int BK = 64;
    extern __shared__ char smem[];
    auto sA    = (__half (*)[128][BK + 8])(smem);
    auto sB    = (__half (*)[BK][128 + 8])(smem + 55296);
    float* sBias = (float*)(smem + 107520);
    float* sW3   = (float*)(smem + 108032);

    const int a  = blockIdx.z;
    const int m0 = blockIdx.y * 128;
    const int n0 = blockIdx.x * 128;

    const __half* A  = IS_L1 ? (g_obs + (size_t)m0 * K)
                             : (g_x1 + ((size_t)a * BATCH + m0) * K);
    const __half* Bw = (IS_L1 ? g_W1 : g_W2) + (size_t)a * K * 1024 + n0;

    const int t = threadIdx.x;
    if (t < 128) {
        sBias[t] = bias[a * 1024 + n0 + t];
        if (!IS_L1) sW3[t] = W3[a * 1024 + n0 + t];
    }

    auto load = [&](int s, int kt) {
#pragma unroll
        for (int i = 0; i < 4; i++) {                       // A: 128 rows x 64 halves
            int c = t + i * 256;
            int r = c >> 3, c8 = (c & 7) * 8;
            cpa16(s32(&sA[s][r][c8]), A + (size_t)r * K + kt + c8);
        }
#pragma unroll
        for (int i = 0; i < 4; i++) {                       // B: 64 rows x 128 halves
            int c = t + i * 256;
            int r = c >> 4, c8 = (c & 15) * 8;
            cpa16(s32(&sB[s][r][c8]), Bw + (size_t)(kt + r) * 1024 + c8);
        }
    };

    const int lane = t & 31, warp = t >> 5;
    const int wm = warp >> 1, wn = warp & 1;

    float acc[2][8][4];
#pragma unroll
    for (int mi = 0; mi < 2; mi++)
#pragma unroll
        for (int ni = 0; ni < 8; ni++)
#pragma unroll
            for (int k = 0; k < 4; k++) acc[mi][ni][k] = 0.f;

    constexpr int NK = K / BK;

    // prologue: fill 2 of 3 stages
    load(0, 0);            cpa_commit();
    if (NK > 1) load(1, BK);
    cpa_commit();

    const int lrow  = lane & 15;
    const int lc8   = (lane >> 4) * 8;
    const int bkrow = lane & 7;
    const int bk8   = ((lane >> 3) & 1) * 8;
    const int bn8   = (lane >> 4) * 8;

    int s = 0;
    for (int kt = 0; kt < NK; kt++) {
        asm volatile("cp.async.wait_group 1;");
        __syncthreads();
        if (kt + 2 < NK) load((s + 2) % 3, (kt + 2) * BK);
        cpa_commit();

#pragma unroll
        for (int ks2 = 0; ks2 < 4; ks2++) {       // warp-staggered k16 order
            const int ks = (ks2 + warp) & 3;
            uint32_t af[2][4];
#pragma unroll
            for (int mi = 0; mi < 2; mi++)
                ldm_x4(af[mi], s32(&sA[s][wm * 32 + mi * 16 + lrow][ks * 16 + lc8]));
            uint32_t bf[4][4];
#pragma unroll
            for (int np = 0; np < 4; np++)
                ldm_x4t(bf[np], s32(&sB[s][ks * 16 + bk8 + bkrow][wn * 64 + np * 16 + bn8]));
#pragma unroll
            for (int mi = 0; mi < 2; mi++)
#pragma unroll
                for (int ni = 0; ni < 8; ni++) {
                    int np = ni >> 1, h = (ni & 1) * 2;
                    mma16816(acc[mi][ni], af[mi], bf[np][h], bf[np][h + 1]);
                }
        }
        s = (s + 1) % 3;
    }

    // ---------------- epilogue ----------------
    if (IS_L1) {
        // smem-transposed coalesced store: tile[128][136] halves reuses sA space.
        __syncthreads();                          // all warps done with smem stages
        auto tile = (__half (*)[136])(smem);
#pragma unroll
        for (int mi = 0; mi < 2; mi++) {
            int r0 = wm * 32 + mi * 16 + (lane >> 2);
#pragma unroll
            for (int ni = 0; ni < 8; ni++) {
                int cl = wn * 64 + ni * 8 + (lane & 3) * 2;
                float b0 = sBias[cl], b1 = sBias[cl + 1];
                float* d = acc[mi][ni];
                *(__half2*)&tile[r0][cl] =
                    __floats2half2_rn(tanh_fast(d[0] + b0), tanh_fast(d[1] + b1));
                *(__half2*)&tile[r0 + 8][cl] =
                    __floats2half2_rn(tanh_fast(d[2] + b0), tanh_fast(d[3] + b1));
            }
        }
        __syncthreads();
        // 256 threads: thread t stores row t>>1, 64-col half (t&1)*64 as 8x16B
        {
            const int row = t >> 1, ch = (t & 1) * 64;
            const __half* src = &tile[row][ch];
            __half* dst = g_x1 + ((size_t)a * BATCH + m0 + row) * 1024 + n0 + ch;
#pragma unroll
            for (int i = 0; i < 8; i++)
                ((uint4*)dst)[i] = *(const uint4*)(src + i * 8);
        }
    } else {
        float pmu[2][2] = {{0.f, 0.f}, {0.f, 0.f}};
#pragma unroll
        for (int mi = 0; mi < 2; mi++)
#pragma unroll
            for (int ni = 0; ni < 8; ni++) {
                int cl = wn * 64 + ni * 8 + (lane & 3) * 2;
                float b0 = sBias[cl], b1 = sBias[cl + 1];
                float w0 = sW3[cl],   w1 = sW3[cl + 1];
                float* d = acc[mi][ni];
                pmu[mi][0] += tanh_fast(d[0] + b0) * w0 + tanh_fast(d[1] + b1) * w1;
                pmu[mi][1] += tanh_fast(d[2] + b0) * w0 + tanh_fast(d[3] + b1) * w1;
            }
#pragma unroll
        for (int o = 1; o <= 2; o <<= 1)
#pragma unroll
            for (int mi = 0; mi < 2; mi++) {
                pmu[mi][0] += __shfl_xor_sync(0xffffffffu, pmu[mi][0], o);
                pmu[mi][1] += __shfl_xor_sync(0xffffffffu, pmu[mi][1], o);
            }
        if ((lane & 3) == 0) {
#pragma unroll
            for (int mi = 0; mi < 2; mi++) {
                int row = m0 + wm * 32 + mi * 16 + (lane >> 2);
                atomicAdd(mu + (size_t)row * 32 + a, pmu[mi][0]);
                atomicAdd(mu + (size_t)(row + 8) * 32 + a, pmu[mi][1]);
            }
        }
    }
}

// ---------------- logp --------------------------------------------------------
__global__ void logp_kernel(const float* __restrict__ mu, const float* __restrict__ act,
                            const float* __restrict__ ls, float* __restrict__ lp) {
    int b = blockIdx.x * blockDim.x + threadIdx.x;
    if (b >= BATCH) return;
    float s = 0.f;
#pragma unroll
    for (int a = 0; a < 32; a++) {
        float l = ls[a];
        float z = (act[b * 32 + a] - mu[b * 32 + a]) * __expf(-l);
        s += -0.5f * (z * z + 1.8378770664093453f) - l;
    }
    lp[b] = s;
}

// ---------------- launch ------------------------------------------------------
extern "C" void kernel_launch(void* const* d_in, const int* in_sizes, int n_in,
                              void* d_out, int out_size) {
    const float* obs  = (const float*)d_in[0];
    const float* act  = (const float*)d_in[1];
    const float* W1   = (const float*)d_in[2];
    const float* b1   = (const float*)d_in[3];
    const float* W2   = (const float*)d_in[4];
    const float* b2   = (const float*)d_in[5];
    const float* W3   = (const float*)d_in[6];
    const float* b3   = (const float*)d_in[7];
    const float* lstd = (const float*)d_in[8];

    float* out = (float*)d_out;
    float* mu  = out;                              // [4096][32]
    float* lp  = out + (size_t)BATCH * ACT;        // [4096]

    static bool init_done = false;
    static cudaStream_t s2;
    static cudaEvent_t eFork, ePre, eJoin;
    if (!init_done) {
        cudaFuncSetAttribute(gemm_kernel<OBS, true>,
                             cudaFuncAttributeMaxDynamicSharedMemorySize, SMEM_BYTES);
        cudaFuncSetAttribute(gemm_kernel<H1D, false>,
                             cudaFuncAttributeMaxDynamicSharedMemorySize, SMEM_BYTES);
        cudaStreamCreateWithFlags(&s2, cudaStreamNonBlocking);
        cudaEventCreateWithFlags(&eFork, cudaEventDisableTiming);
        cudaEventCreateWithFlags(&ePre, cudaEventDisableTiming);
        cudaEventCreateWithFlags(&eJoin, cudaEventDisableTiming);
        init_done = true;
    }

    const int NW1 = ACT * OBS * H1D;               // 16.8M elems
    const int HW1 = NW1 / 2;

    // Fork: s2 converts obs + W1-half2 (gemm1 deps), then W2 + mu init (gemm2
    // deps, hidden under gemm1). Main converts W1-half1 concurrently.
    cudaEventRecord(eFork, 0);
    cudaStreamWaitEvent(s2, eFork, 0);
    f2h_kernel<<<(BATCH * OBS) / 2048, 256, 0, s2>>>(obs, 0, 0, BATCH * OBS);
    f2h_kernel<<<HW1 / 2048, 256, 0, s2>>>(W1, 1, HW1, HW1);
    cudaEventRecord(ePre, s2);
    f2h_kernel<<<(ACT * H1D * H2D) / 2048, 256, 0, s2>>>(W2, 2, 0, ACT * H1D * H2D);
    mu_init_kernel<<<(BATCH * ACT) / 256, 256, 0, s2>>>(b3, mu);
    cudaEventRecord(eJoin, s2);

    // Main stream: W1-half1 runs parallel to s2's obs + W1-half2.
    f2h_kernel<<<HW1 / 2048, 256>>>(W1, 1, 0, HW1);
    cudaStreamWaitEvent(0, ePre, 0);

    gemm_kernel<OBS, true><<<dim3(8, 32, 32), 256, SMEM_BYTES>>>(b1, nullptr, nullptr);

    // Join: gemm2 needs W2 (s2) and x1 (main stream).
    cudaStreamWaitEvent(0, eJoin, 0);

    gemm_kernel<H1D, false><<<dim3(8, 32, 32), 256, SMEM_BYTES>>>(b2, W3, mu);

    logp_kernel<<<(BATCH + 255) / 256, 256>>>(mu, act, lstd, lp);
}